// round 1
// baseline (speedup 1.0000x reference)
#include <cuda_runtime.h>
#include <cuda_bf16.h>

// SimCLR loss: B=4096, D=128, T=0.1
// z = [normalize(x_i); normalize(x_j)]  (8192 x 128)
// sim = z z^T ; denom_r = sum_{j != r} exp(sim_rj * 10)
// pos_r = sim[r, r ^ 4096]  (B is a power of 2)
// loss = mean_r( log(denom_r) - pos_r * 10 )

#define BDIM 4096
#define N2   8192
#define DDIM 128
#define INV_T 10.0f

// Scratch (no cudaMalloc allowed)
__device__ float g_z[N2 * DDIM];       // 4 MB normalized rows
__device__ float g_rowsum[N2];         // full exp row sums (incl diagonal)
__device__ float g_diag[N2];           // sim_ii as computed
__device__ float g_pos[N2];            // sim[r, r^B]

// ---------------------------------------------------------------------------
// Kernel 1: row L2 normalization. One warp per row, float4 per lane.
// ---------------------------------------------------------------------------
__global__ void norm_kernel(const float* __restrict__ xi,
                            const float* __restrict__ xj) {
    int row  = blockIdx.x * 8 + (threadIdx.x >> 5);
    int lane = threadIdx.x & 31;
    const float* src = (row < BDIM) ? (xi + (size_t)row * DDIM)
                                    : (xj + (size_t)(row - BDIM) * DDIM);
    float4 v = reinterpret_cast<const float4*>(src)[lane];
    float s = v.x * v.x + v.y * v.y + v.z * v.z + v.w * v.w;
    #pragma unroll
    for (int o = 16; o > 0; o >>= 1)
        s += __shfl_xor_sync(0xFFFFFFFFu, s, o);
    float n   = sqrtf(s);
    float inv = 1.0f / fmaxf(n, 1e-12f);
    float4 o4 = make_float4(v.x * inv, v.y * inv, v.z * inv, v.w * inv);
    reinterpret_cast<float4*>(g_z + (size_t)row * DDIM)[lane] = o4;
}

// ---------------------------------------------------------------------------
// Kernel 2: fused GEMM + exp row-sum.
// Grid = 128 blocks; block owns 64 rows, loops over 128 column tiles of 64.
// 256 threads (16x16), each computing a 4x4 micro-tile. K=128 fully in smem.
// ---------------------------------------------------------------------------
#define BM 64
#define BN 64
#define LDA (DDIM + 4)   // pad to dodge bank conflicts

__global__ __launch_bounds__(256, 1)
void simgemm_kernel() {
    __shared__ float As[BM][LDA];
    __shared__ float Bs[BN][LDA];

    const int tid = threadIdx.x;
    const int tx  = tid & 15;          // column group
    const int ty  = tid >> 4;          // row group
    const int rowBase = blockIdx.x * BM;

    // Load A tile once (64 rows x 128 cols), coalesced float4.
    for (int i = tid; i < BM * (DDIM / 4); i += 256) {
        int r  = i >> 5;               // 0..63
        int kq = (i & 31) << 2;        // 0..124 step 4
        float4 v = *reinterpret_cast<const float4*>(
            &g_z[(size_t)(rowBase + r) * DDIM + kq]);
        *reinterpret_cast<float4*>(&As[r][kq]) = v;
    }

    float acc[4] = {0.f, 0.f, 0.f, 0.f};

    for (int t = 0; t < N2 / BN; t++) {
        const int colBase = t * BN;
        __syncthreads();               // previous tile's reads done
        for (int i = tid; i < BN * (DDIM / 4); i += 256) {
            int r  = i >> 5;
            int kq = (i & 31) << 2;
            *reinterpret_cast<float4*>(&Bs[r][kq]) =
                *reinterpret_cast<const float4*>(
                    &g_z[(size_t)(colBase + r) * DDIM + kq]);
        }
        __syncthreads();

        float c[4][4] = {};
        #pragma unroll 8
        for (int k = 0; k < DDIM; k++) {
            float a[4], b[4];
            #pragma unroll
            for (int i = 0; i < 4; i++) a[i] = As[ty * 4 + i][k];
            #pragma unroll
            for (int j = 0; j < 4; j++) b[j] = Bs[tx * 4 + j][k];
            #pragma unroll
            for (int i = 0; i < 4; i++)
                #pragma unroll
                for (int j = 0; j < 4; j++)
                    c[i][j] = fmaf(a[i], b[j], c[i][j]);
        }

        #pragma unroll
        for (int i = 0; i < 4; i++) {
            const int r = rowBase + ty * 4 + i;
            #pragma unroll
            for (int j = 0; j < 4; j++) {
                const int gc = colBase + tx * 4 + j;
                const float s = c[i][j];
                acc[i] += __expf(s * INV_T);
                if (gc == r)            g_diag[r] = s;   // unique writer
                if (gc == (r ^ BDIM))   g_pos[r]  = s;   // unique writer
            }
        }
    }

    // Reduce acc across the 16 tx threads per row. Reuse As.
    __syncthreads();
    #pragma unroll
    for (int i = 0; i < 4; i++)
        As[ty * 4 + i][tx] = acc[i];
    __syncthreads();
    if (tx == 0) {
        #pragma unroll
        for (int i = 0; i < 4; i++) {
            const int r = rowBase + ty * 4 + i;
            float s = 0.f;
            #pragma unroll
            for (int q = 0; q < 16; q++) s += As[ty * 4 + i][q];
            g_rowsum[r] = s;
        }
    }
}

// ---------------------------------------------------------------------------
// Kernel 3: final scalar reduction.
// ---------------------------------------------------------------------------
__global__ void loss_kernel(float* __restrict__ out) {
    __shared__ float sred[256];
    float s = 0.f;
    for (int r = threadIdx.x; r < N2; r += 256) {
        float denom = g_rowsum[r] - __expf(g_diag[r] * INV_T);
        s += logf(denom) - g_pos[r] * INV_T;
    }
    sred[threadIdx.x] = s;
    __syncthreads();
    for (int o = 128; o > 0; o >>= 1) {
        if (threadIdx.x < o) sred[threadIdx.x] += sred[threadIdx.x + o];
        __syncthreads();
    }
    if (threadIdx.x == 0) out[0] = sred[0] / (float)N2;
}

// ---------------------------------------------------------------------------
extern "C" void kernel_launch(void* const* d_in, const int* in_sizes, int n_in,
                              void* d_out, int out_size) {
    const float* xi = (const float*)d_in[0];
    const float* xj = (const float*)d_in[1];
    float* out = (float*)d_out;

    norm_kernel<<<N2 / 8, 256>>>(xi, xj);
    simgemm_kernel<<<N2 / BM, 256>>>();
    loss_kernel<<<1, 256>>>(out);
}

// round 5
// speedup vs baseline: 26.3317x; 26.3317x over previous
#include <cuda_runtime.h>
#include <cuda_bf16.h>
#include <cstdint>

// SimCLR loss, B=4096, D=128, T=0.1.
// compute_103-safe path: mma.sync.m16n8k16 bf16 (no tcgen05 — 'a'-gated).
// z = [norm(x_i); norm(x_j)] (8192x128) -> bf16
// sim = z z^T ; rowsum_r = sum_j exp(sim_rj*10) (incl diag, subtracted later)
// loss = mean( log(rowsum - exp(diag*10)) - pos*10 ),  pos_r = sim[r, r^4096]

#define BDIM 4096
#define N2   8192
#define DDIM 128
#define MT   128                 // rows per CTA
#define CTILE 128                // cols per tile
#define NHALF 4096               // cols per CTA (grid.y = 2)
#define NTILES (NHALF / CTILE)   // 32
#define RSB  272                 // smem row stride bytes (128 bf16 + 16B pad)

// 10/ln2: exp(10*s) == 2^(s*14.4269504089)
#define LOG2E10 14.42695040888963f

// ---- scratch (__device__ globals; no cudaMalloc allowed) ----
__device__ __nv_bfloat16 g_zb[N2 * DDIM];   // 2 MB normalized bf16 rows
__device__ float g_psum[2 * N2];
__device__ float g_diag[N2];
__device__ float g_pos[N2];

// ---- helpers ----
__device__ __forceinline__ uint32_t smem_u32(const void* p) {
    uint32_t a;
    asm("{ .reg .u64 t; cvta.to.shared.u64 t, %1; cvt.u32.u64 %0, t; }"
        : "=r"(a) : "l"(p));
    return a;
}
// exp(10*s) — used identically in epilogue and loss kernel so the diag
// term cancels bit-exactly.
__device__ __forceinline__ float expt(float s) {
    float e;
    asm("ex2.approx.ftz.f32 %0, %1;" : "=f"(e) : "f"(s * LOG2E10));
    return e;
}

#define CPA16(dst, src) \
    asm volatile("cp.async.cg.shared.global [%0], [%1], 16;" \
                 :: "r"(dst), "l"(src) : "memory")
#define CPA_COMMIT() asm volatile("cp.async.commit_group;" ::: "memory")
#define CPA_WAIT0()  asm volatile("cp.async.wait_group 0;" ::: "memory")

#define LDSM4(r0, r1, r2, r3, a) \
    asm volatile("ldmatrix.sync.aligned.m8n8.x4.shared.b16 {%0,%1,%2,%3}, [%4];" \
                 : "=r"(r0), "=r"(r1), "=r"(r2), "=r"(r3) : "r"(a))

__device__ __forceinline__ void mma16816(float* d, const uint32_t* a,
                                         uint32_t b0, uint32_t b1) {
    asm volatile(
        "mma.sync.aligned.m16n8k16.row.col.f32.bf16.bf16.f32 "
        "{%0,%1,%2,%3}, {%4,%5,%6,%7}, {%8,%9}, {%0,%1,%2,%3};"
        : "+f"(d[0]), "+f"(d[1]), "+f"(d[2]), "+f"(d[3])
        : "r"(a[0]), "r"(a[1]), "r"(a[2]), "r"(a[3]), "r"(b0), "r"(b1));
}

// ---- SMEM layout (dynamic): A 128x272B, then two B buffers ----
#define SM_A   0
#define SM_B0  34816
#define SM_B1  69632
#define SM_TOTAL 104448

// ---------------------------------------------------------------------------
// Kernel 1: L2 normalize -> bf16. One warp per row.
// ---------------------------------------------------------------------------
__global__ void norm_kernel(const float* __restrict__ xi,
                            const float* __restrict__ xj) {
    int row  = blockIdx.x * 8 + (threadIdx.x >> 5);
    int lane = threadIdx.x & 31;
    const float* src = (row < BDIM) ? (xi + (size_t)row * DDIM)
                                    : (xj + (size_t)(row - BDIM) * DDIM);
    float4 v = reinterpret_cast<const float4*>(src)[lane];
    float s = v.x * v.x + v.y * v.y + v.z * v.z + v.w * v.w;
    #pragma unroll
    for (int o = 16; o > 0; o >>= 1) s += __shfl_xor_sync(0xFFFFFFFFu, s, o);
    float inv = 1.0f / fmaxf(sqrtf(s), 1e-12f);
    __nv_bfloat16 o4[4];
    o4[0] = __float2bfloat16(v.x * inv);
    o4[1] = __float2bfloat16(v.y * inv);
    o4[2] = __float2bfloat16(v.z * inv);
    o4[3] = __float2bfloat16(v.w * inv);
    *reinterpret_cast<uint2*>(g_zb + (size_t)row * DDIM + lane * 4) =
        *reinterpret_cast<uint2*>(o4);
}

// ---------------------------------------------------------------------------
// Kernel 2: HMMA GEMM + fused exp row-sum epilogue.
// grid (64, 2); 256 threads = 8 warps as 4 row-warps x 2 col-warps.
// Warp tile 32x64. A tile register-resident for the whole kernel.
// ---------------------------------------------------------------------------
__global__ void __launch_bounds__(256, 1) simgemm_kernel() {
    extern __shared__ char smem[];
    const uint32_t sb = smem_u32(smem);
    const int tid  = threadIdx.x;
    const int lane = tid & 31;
    const int w    = tid >> 5;
    const int wr   = w & 3;        // row warp (32 rows each)
    const int wc   = w >> 2;       // col warp (64 cols each)
    const int mbase = blockIdx.x * MT;
    const int half  = blockIdx.y;
    const int cbase = half * NHALF;

    // ldmatrix lane addressing (shared by A and B, non-trans):
    // lanes 0-7: rows 0-7 k-chunk lo | 8-15: rows 8-15 lo | 16-23: 0-7 hi | 24-31: 8-15 hi
    const int rrow = (lane & 7) + ((lane >> 3) & 1) * 8;
    const int csel = lane >> 4;
    const int rquad = lane >> 2;
    const int cpair = (lane & 3) * 2;

    // ---- load A tile + B tile 0 ----
    #pragma unroll
    for (int i = 0; i < 8; i++) {
        int idx = tid + i * 256;
        int r = idx >> 4, c = idx & 15;
        CPA16(sb + SM_A + r * RSB + c * 16,
              g_zb + (size_t)(mbase + r) * DDIM + c * 8);
    }
    #pragma unroll
    for (int i = 0; i < 8; i++) {
        int idx = tid + i * 256;
        int r = idx >> 4, c = idx & 15;
        CPA16(sb + SM_B0 + r * RSB + c * 16,
              g_zb + (size_t)(cbase + r) * DDIM + c * 8);
    }
    CPA_COMMIT();
    CPA_WAIT0();
    __syncthreads();

    // ---- A fragments: 32 rows x K=128, resident in registers ----
    uint32_t af[8][2][4];
    #pragma unroll
    for (int ks = 0; ks < 8; ks++)
        #pragma unroll
        for (int i = 0; i < 2; i++) {
            uint32_t a = sb + SM_A + (wr * 32 + i * 16 + rrow) * RSB
                       + (ks * 2 + csel) * 16;
            LDSM4(af[ks][i][0], af[ks][i][1], af[ks][i][2], af[ks][i][3], a);
        }

    float rsum[4] = {0.f, 0.f, 0.f, 0.f};

    for (int t = 0; t < NTILES; t++) {
        const uint32_t sbB = sb + ((t & 1) ? SM_B1 : SM_B0);

        // prefetch B tile t+1 into the other buffer
        if (t + 1 < NTILES) {
            const uint32_t sbN = sb + (((t + 1) & 1) ? SM_B1 : SM_B0);
            const int cn = cbase + (t + 1) * CTILE;
            #pragma unroll
            for (int i = 0; i < 8; i++) {
                int idx = tid + i * 256;
                int r = idx >> 4, c = idx & 15;
                CPA16(sbN + r * RSB + c * 16,
                      g_zb + (size_t)(cn + r) * DDIM + c * 8);
            }
            CPA_COMMIT();
        }

        float acc[2][8][4];
        #pragma unroll
        for (int i = 0; i < 2; i++)
            #pragma unroll
            for (int j = 0; j < 8; j++)
                #pragma unroll
                for (int c = 0; c < 4; c++) acc[i][j][c] = 0.f;

        #pragma unroll
        for (int ks = 0; ks < 8; ks++) {
            uint32_t bf[4][4];
            #pragma unroll
            for (int g = 0; g < 4; g++) {
                uint32_t a = sbB + (wc * 64 + g * 16 + rrow) * RSB
                           + (ks * 2 + csel) * 16;
                LDSM4(bf[g][0], bf[g][1], bf[g][2], bf[g][3], a);
            }
            #pragma unroll
            for (int i = 0; i < 2; i++)
                #pragma unroll
                for (int j = 0; j < 8; j++)
                    mma16816(acc[i][j], af[ks][i],
                             bf[j >> 1][j & 1], bf[j >> 1][(j & 1) + 2]);
        }

        // ---- epilogue: exp row-sums; diag/pos only in flagged tiles ----
        const int ct = cbase + t * CTILE;
        #pragma unroll
        for (int i = 0; i < 2; i++)
            #pragma unroll
            for (int j = 0; j < 8; j++)
                #pragma unroll
                for (int c = 0; c < 4; c++)
                    rsum[i * 2 + (c >> 1)] += expt(acc[i][j][c]);

        if (ct == mbase || ct == (mbase ^ BDIM)) {
            #pragma unroll
            for (int i = 0; i < 2; i++)
                #pragma unroll
                for (int j = 0; j < 8; j++)
                    #pragma unroll
                    for (int c = 0; c < 4; c++) {
                        int row = mbase + wr * 32 + i * 16 + (c >> 1) * 8 + rquad;
                        int col = ct + wc * 64 + j * 8 + cpair + (c & 1);
                        float s = acc[i][j][c];
                        if (col == row)           g_diag[row] = s;
                        if (col == (row ^ BDIM))  g_pos[row]  = s;
                    }
        }

        if (t + 1 < NTILES) { CPA_WAIT0(); __syncthreads(); }
    }

    // ---- reduce: lanes sharing rows (lane&3), then the 2 col-warps ----
    #pragma unroll
    for (int q = 0; q < 4; q++) {
        rsum[q] += __shfl_xor_sync(0xFFFFFFFFu, rsum[q], 1);
        rsum[q] += __shfl_xor_sync(0xFFFFFFFFu, rsum[q], 2);
    }
    float* red = reinterpret_cast<float*>(smem);   // reuse A region: [128][2]
    __syncthreads();
    if ((lane & 3) == 0) {
        #pragma unroll
        for (int q = 0; q < 4; q++) {
            int rloc = wr * 32 + (q >> 1) * 16 + (q & 1) * 8 + rquad;
            red[rloc * 2 + wc] = rsum[q];
        }
    }
    __syncthreads();
    if (tid < 128)
        g_psum[half * N2 + mbase + tid] = red[tid * 2] + red[tid * 2 + 1];
}

// ---------------------------------------------------------------------------
// Kernel 3: final scalar reduction.
// ---------------------------------------------------------------------------
__global__ void loss_kernel(float* __restrict__ out) {
    __shared__ float sred[256];
    float s = 0.f;
    for (int r = threadIdx.x; r < N2; r += 256) {
        float denom = g_psum[r] + g_psum[N2 + r] - expt(g_diag[r]);
        s += logf(denom) - g_pos[r] * 10.0f;
    }
    sred[threadIdx.x] = s;
    __syncthreads();
    for (int o = 128; o > 0; o >>= 1) {
        if (threadIdx.x < o) sred[threadIdx.x] += sred[threadIdx.x + o];
        __syncthreads();
    }
    if (threadIdx.x == 0) out[0] = sred[0] / (float)N2;
}

// ---------------------------------------------------------------------------
extern "C" void kernel_launch(void* const* d_in, const int* in_sizes, int n_in,
                              void* d_out, int out_size) {
    const float* xi = (const float*)d_in[0];
    const float* xj = (const float*)d_in[1];
    float* out = (float*)d_out;

    cudaFuncSetAttribute(simgemm_kernel,
                         cudaFuncAttributeMaxDynamicSharedMemorySize, SM_TOTAL);

    norm_kernel<<<N2 / 8, 256>>>(xi, xj);
    simgemm_kernel<<<dim3(N2 / MT, 2), 256, SM_TOTAL>>>();
    loss_kernel<<<1, 256>>>(out);
}